// round 1
// baseline (speedup 1.0000x reference)
#include <cuda_runtime.h>
#include <cuda_bf16.h>
#include <cstdint>

// RotationComponent: w_rotated = w @ rot, a_rotated = x @ rot, where rot is a
// normalized randomized Hadamard matrix: rot[i,j] = H[i,j] * rot[0,j] with H
// the 4096x4096 Sylvester Hadamard (symmetric, H[0,:] = +1). Hence
//   (v @ rot)[j] = FWHT(v)[j] * rot[0,j]
// computed exactly from the given rot (scales read from its first row).
//
// One CTA per row. 12 FWHT stages over 4096 elements:
//   - bits 11..8 : register butterflies (16 regs/thread)
//   - bits  4..0 : warp shuffle butterflies
//   - smem transpose (single __syncthreads round-trip)
//   - bits  7..5 : register butterflies in the remapped layout
// Finally scale by rot[0, idx] and store.

#define DIM 4096
#define W_ROWS 4096
#define X_ROWS 8192   // 4 * 2048
#define THREADS 256

__global__ __launch_bounds__(THREADS)
void fwht_rotate_kernel(const float* __restrict__ w,
                        const float* __restrict__ x,
                        const float* __restrict__ rot,
                        float* __restrict__ out)
{
    __shared__ float smem[DIM];

    const int row  = blockIdx.x;
    const int tid  = threadIdx.x;
    const int lane = tid & 31;
    const int warp = tid >> 5;

    const float* src = (row < W_ROWS)
        ? (w + (size_t)row * DIM)
        : (x + (size_t)(row - W_ROWS) * DIM);

    // ---- Load: v[r] holds element index i = r*256 + tid (coalesced) ----
    float v[16];
    #pragma unroll
    for (int r = 0; r < 16; r++) {
        v[r] = src[r * THREADS + tid];
    }

    // ---- Stage A: butterflies on bits 11..8 (register index r) ----
    #pragma unroll
    for (int m = 8; m >= 1; m >>= 1) {
        #pragma unroll
        for (int r = 0; r < 16; r++) {
            if ((r & m) == 0) {
                float a = v[r];
                float b = v[r | m];
                v[r]     = a + b;
                v[r | m] = a - b;
            }
        }
    }

    // ---- Stage B: butterflies on bits 4..0 (lane index) via shfl_xor ----
    #pragma unroll
    for (int m = 16; m >= 1; m >>= 1) {
        const bool hi = (lane & m) != 0;
        #pragma unroll
        for (int r = 0; r < 16; r++) {
            float other = __shfl_xor_sync(0xffffffffu, v[r], m);
            v[r] = hi ? (other - v[r]) : (v[r] + other);
        }
    }

    // ---- Transpose through smem to expose bits 7..5 as register bits ----
    // Write at logical index i = r*256 + tid (conflict-free: lane-consecutive).
    #pragma unroll
    for (int r = 0; r < 16; r++) {
        smem[r * THREADS + tid] = v[r];
    }
    __syncthreads();

    // Re-read with i' = warp*512 + r2*32 + lane:
    //   lane -> bits 4..0, r2 -> bits 8..5, warp -> bits 11..9.
    // Remaining butterfly bits 7,6,5 are r2 bits 2,1,0.
    const int base_idx = warp * 512 + lane;
    #pragma unroll
    for (int r2 = 0; r2 < 16; r2++) {
        v[r2] = smem[base_idx + r2 * 32];
    }

    // ---- Stage C: butterflies on bits 7..5 (r2 bits 2..0) ----
    #pragma unroll
    for (int m = 4; m >= 1; m >>= 1) {
        #pragma unroll
        for (int r2 = 0; r2 < 16; r2++) {
            if ((r2 & m) == 0) {
                float a = v[r2];
                float b = v[r2 | m];
                v[r2]     = a + b;
                v[r2 | m] = a - b;
            }
        }
    }

    // ---- Scale by rot[0, idx] and store (coalesced, 128B per warp/r2) ----
    float* dst = out + (size_t)row * DIM;
    #pragma unroll
    for (int r2 = 0; r2 < 16; r2++) {
        const int idx = base_idx + r2 * 32;
        dst[idx] = v[r2] * __ldg(&rot[idx]);
    }
}

extern "C" void kernel_launch(void* const* d_in, const int* in_sizes, int n_in,
                              void* d_out, int out_size)
{
    const float* w   = (const float*)d_in[0];   // [4096, 4096]
    const float* x   = (const float*)d_in[1];   // [4, 2048, 4096]
    const float* rot = (const float*)d_in[2];   // [4096, 4096]
    float* out = (float*)d_out;                 // w_rotated (4096*4096) then a_rotated (8192*4096)

    (void)in_sizes; (void)n_in; (void)out_size;

    fwht_rotate_kernel<<<W_ROWS + X_ROWS, THREADS>>>(w, x, rot, out);
}